// round 3
// baseline (speedup 1.0000x reference)
#include <cuda_runtime.h>

typedef unsigned long long u64;

__device__ __forceinline__ u64 pk2(float lo, float hi){
  u64 r; asm("mov.b64 %0, {%1,%2};" : "=l"(r) : "f"(lo), "f"(hi)); return r;
}
__device__ __forceinline__ void upk2(u64 v, float& lo, float& hi){
  asm("mov.b64 {%0,%1}, %2;" : "=f"(lo), "=f"(hi) : "l"(v));
}
__device__ __forceinline__ u64 fma2(u64 a, u64 b, u64 c){
  u64 d; asm("fma.rn.f32x2 %0, %1, %2, %3;" : "=l"(d) : "l"(a), "l"(b), "l"(c)); return d;
}
__device__ __forceinline__ u64 mul2(u64 a, u64 b){
  u64 d; asm("mul.rn.f32x2 %0, %1, %2;" : "=l"(d) : "l"(a), "l"(b)); return d;
}

// XOR swizzle: 1024 positions x 32 rows, 128B per position (one full bank cycle).
// quad = row>>2. Conflict-free for all four pass access patterns (lanes in any
// 8-lane LDS phase have pos distinct in the bits this mixes).
__device__ __forceinline__ int fsw(int pos){ return (pos ^ (pos >> 3) ^ (pos >> 6)) & 7; }
__device__ __forceinline__ int widx(int pos, int quad){
  return (pos << 5) + (((quad ^ fsw(pos)) & 7) << 2);
}

// One butterfly pair: x0' = t00*x0 + t01*x1 ; x1' = t10*x0 + t11*x1
// m = {t00,t01,t10,t11} packed f32x2 (duplicated across the 2 batch lanes).
__device__ __forceinline__ void bfly(u64& x0, u64& x1, const u64* m){
  u64 a = x0, b = x1;
  x0 = fma2(m[0], a, mul2(m[1], b));
  x1 = fma2(m[2], a, mul2(m[3], b));
}

// 3 stages on 8 local elements (local strides 1,2,4 in the k-index).
// m[0..15]=stageA (pairs (0,1)(2,3)(4,5)(6,7)), m[16..31]=stageB ((0,2)(1,3)(4,6)(5,7)),
// m[32..47]=stageC ((0,4)(1,5)(2,6)(3,7)).
__device__ __forceinline__ void radix8(u64 v[8], const u64 m[48]){
  bfly(v[0],v[1], m+ 0); bfly(v[2],v[3], m+ 4); bfly(v[4],v[5], m+ 8); bfly(v[6],v[7], m+12);
  bfly(v[0],v[2], m+16); bfly(v[1],v[3], m+20); bfly(v[4],v[6], m+24); bfly(v[5],v[7], m+28);
  bfly(v[0],v[4], m+32); bfly(v[1],v[5], m+36); bfly(v[2],v[6], m+40); bfly(v[3],v[7], m+44);
}

__device__ __forceinline__ void load_mats(const float4* __restrict__ tw4,
                                          int s0, int pbase, int pstride, u64 m[48]){
  #pragma unroll
  for (int s = 0; s < 3; s++){
    #pragma unroll
    for (int q = 0; q < 4; q++){
      float4 t = tw4[(s0 + s) * 512 + pbase + q * pstride];
      u64* mm = m + (s * 4 + q) * 4;
      mm[0] = pk2(t.x, t.x); mm[1] = pk2(t.y, t.y);
      mm[2] = pk2(t.z, t.z); mm[3] = pk2(t.w, t.w);
    }
  }
}

__global__ __launch_bounds__(256, 1)
void butterfly_kernel(const float* __restrict__ x,
                      const float* __restrict__ tw,
                      const float* __restrict__ bias,
                      float* __restrict__ out)
{
  extern __shared__ float sdata[];  // 1024 pos * 32 rows * 4B = 128KB, swizzled
  const float4* tw4 = (const float4*)tw;
  const int tid  = threadIdx.x;
  const int o    = tid & 127;      // position-octet index within the row
  const int half = tid >> 7;       // which 16 of the 32 rows this thread owns
  const long long rowbase = (long long)blockIdx.x * 32 + (long long)half * 16;

  u64 m[48];

  // ================= PASS 1: stages 0-2 (stride 1,2,4), global -> smem ======
  // Thread owns positions 8o..8o+7 (contiguous octet). Pairs for all 3 stages
  // are twiddle[s][4o+q], q=0..3.
  load_mats(tw4, 0, 4 * o, 1, m);

  #pragma unroll
  for (int g = 0; g < 4; g++){
    u64 v01[8], v23[8];
    const float* base = x + (rowbase + 4 * g) * 1024 + 8 * o;
    float4 a0 = *(const float4*)(base        );
    float4 b0 = *(const float4*)(base +    4 );
    float4 a1 = *(const float4*)(base + 1024 );
    float4 b1 = *(const float4*)(base + 1028 );
    float4 a2 = *(const float4*)(base + 2048 );
    float4 b2 = *(const float4*)(base + 2052 );
    float4 a3 = *(const float4*)(base + 3072 );
    float4 b3 = *(const float4*)(base + 3076 );
    v01[0]=pk2(a0.x,a1.x); v01[1]=pk2(a0.y,a1.y); v01[2]=pk2(a0.z,a1.z); v01[3]=pk2(a0.w,a1.w);
    v01[4]=pk2(b0.x,b1.x); v01[5]=pk2(b0.y,b1.y); v01[6]=pk2(b0.z,b1.z); v01[7]=pk2(b0.w,b1.w);
    v23[0]=pk2(a2.x,a3.x); v23[1]=pk2(a2.y,a3.y); v23[2]=pk2(a2.z,a3.z); v23[3]=pk2(a2.w,a3.w);
    v23[4]=pk2(b2.x,b3.x); v23[5]=pk2(b2.y,b3.y); v23[6]=pk2(b2.z,b3.z); v23[7]=pk2(b2.w,b3.w);

    radix8(v01, m); radix8(v23, m);

    const int quad = half * 4 + g;
    #pragma unroll
    for (int c = 0; c < 8; c++){
      ulonglong2 u; u.x = v01[c]; u.y = v23[c];
      *(ulonglong2*)&sdata[widx(8 * o + c, quad)] = u;
    }
  }
  __syncthreads();

  // ================= PASS 2: stages 3-5 (stride 8,16,32) ====================
  // Thread owns pos = 64b + 8k + j, k=0..7 (b=o>>3, j=o&7).
  // All 3 stages use twiddle[s][32b + 8q + j].
  {
    const int bb = o >> 3, j = o & 7;
    load_mats(tw4, 3, 32 * bb + j, 8, m);
    #pragma unroll
    for (int g = 0; g < 4; g++){
      const int quad = half * 4 + g;
      u64 v01[8], v23[8];
      #pragma unroll
      for (int k = 0; k < 8; k++){
        ulonglong2 u = *(ulonglong2*)&sdata[widx(64 * bb + 8 * k + j, quad)];
        v01[k] = u.x; v23[k] = u.y;
      }
      radix8(v01, m); radix8(v23, m);
      #pragma unroll
      for (int k = 0; k < 8; k++){
        ulonglong2 u; u.x = v01[k]; u.y = v23[k];
        *(ulonglong2*)&sdata[widx(64 * bb + 8 * k + j, quad)] = u;
      }
    }
  }
  __syncthreads();

  // ================= PASS 3: stages 6-8 (stride 64,128,256) =================
  // Thread owns pos = 512B + 64k + j, k=0..7 (B=o>>6, j=o&63).
  // All 3 stages use twiddle[s][256B + 64q + j].
  {
    const int BB = o >> 6, j = o & 63;
    load_mats(tw4, 6, 256 * BB + j, 64, m);
    #pragma unroll
    for (int g = 0; g < 4; g++){
      const int quad = half * 4 + g;
      u64 v01[8], v23[8];
      #pragma unroll
      for (int k = 0; k < 8; k++){
        ulonglong2 u = *(ulonglong2*)&sdata[widx(512 * BB + 64 * k + j, quad)];
        v01[k] = u.x; v23[k] = u.y;
      }
      radix8(v01, m); radix8(v23, m);
      #pragma unroll
      for (int k = 0; k < 8; k++){
        ulonglong2 u; u.x = v01[k]; u.y = v23[k];
        *(ulonglong2*)&sdata[widx(512 * BB + 64 * k + j, quad)] = u;
      }
    }
  }
  __syncthreads();

  // ================= PASS 4: stage 9 (stride 512) + bias -> global ==========
  // Pairs (o+128jj, o+128jj+512), jj=0..3; twiddle[9][o+128jj].
  {
    u64 m9[16], bl[4], bh[4];
    #pragma unroll
    for (int jj = 0; jj < 4; jj++){
      float4 t = tw4[9 * 512 + o + 128 * jj];
      m9[jj*4+0] = pk2(t.x,t.x); m9[jj*4+1] = pk2(t.y,t.y);
      m9[jj*4+2] = pk2(t.z,t.z); m9[jj*4+3] = pk2(t.w,t.w);
      float b0v = bias[o + 128 * jj];
      float b1v = bias[o + 128 * jj + 512];
      bl[jj] = pk2(b0v, b0v); bh[jj] = pk2(b1v, b1v);
    }
    #pragma unroll
    for (int g = 0; g < 4; g++){
      const int quad = half * 4 + g;
      float* orow = out + (rowbase + 4 * g) * 1024;
      #pragma unroll
      for (int jj = 0; jj < 4; jj++){
        const int plo = o + 128 * jj, phi = plo + 512;
        ulonglong2 ulo = *(ulonglong2*)&sdata[widx(plo, quad)];
        ulonglong2 uhi = *(ulonglong2*)&sdata[widx(phi, quad)];
        const u64* mm = m9 + jj * 4;
        u64 y0a = fma2(mm[0], ulo.x, fma2(mm[1], uhi.x, bl[jj]));
        u64 y0b = fma2(mm[0], ulo.y, fma2(mm[1], uhi.y, bl[jj]));
        u64 y1a = fma2(mm[2], ulo.x, fma2(mm[3], uhi.x, bh[jj]));
        u64 y1b = fma2(mm[2], ulo.y, fma2(mm[3], uhi.y, bh[jj]));
        float f0, f1, f2, f3;
        upk2(y0a, f0, f1); upk2(y0b, f2, f3);
        orow[0*1024 + plo] = f0; orow[1*1024 + plo] = f1;
        orow[2*1024 + plo] = f2; orow[3*1024 + plo] = f3;
        upk2(y1a, f0, f1); upk2(y1b, f2, f3);
        orow[0*1024 + phi] = f0; orow[1*1024 + phi] = f1;
        orow[2*1024 + phi] = f2; orow[3*1024 + phi] = f3;
      }
    }
  }
}

extern "C" void kernel_launch(void* const* d_in, const int* in_sizes, int n_in,
                              void* d_out, int out_size)
{
  const float* x    = (const float*)d_in[0];   // (32768, 1024) f32
  const float* tw   = (const float*)d_in[1];   // (1, 10, 512, 2, 2) f32
  const float* bias = (const float*)d_in[2];   // (1024,) f32
  float* out = (float*)d_out;                  // (32768, 1024) f32

  const int batch = in_sizes[0] / 1024;
  const int smem_bytes = 1024 * 32 * 4;        // 128KB

  cudaFuncSetAttribute(butterfly_kernel,
                       cudaFuncAttributeMaxDynamicSharedMemorySize, smem_bytes);
  butterfly_kernel<<<batch / 32, 256, smem_bytes>>>(x, tw, bias, out);
}

// round 4
// speedup vs baseline: 1.0845x; 1.0845x over previous
#include <cuda_runtime.h>

typedef unsigned long long u64;

__device__ __forceinline__ u64 pk2(float lo, float hi){
  u64 r; asm volatile("mov.b64 %0, {%1,%2};" : "=l"(r) : "f"(lo), "f"(hi)); return r;
}
__device__ __forceinline__ void upk2(u64 v, float& lo, float& hi){
  asm("mov.b64 {%0,%1}, %2;" : "=f"(lo), "=f"(hi) : "l"(v));
}
__device__ __forceinline__ u64 fma2(u64 a, u64 b, u64 c){
  u64 d; asm("fma.rn.f32x2 %0, %1, %2, %3;" : "=l"(d) : "l"(a), "l"(b), "l"(c)); return d;
}
__device__ __forceinline__ u64 mul2(u64 a, u64 b){
  u64 d; asm("mul.rn.f32x2 %0, %1, %2;" : "=l"(d) : "l"(a), "l"(b)); return d;
}

// 16 rows per CTA stored as 4 quads of 4 rows; one 16B slot per (position, quad).
// slot = (quad ^ (p>>1) ^ (p>>3)) & 3 keeps every pass's 8-lane LDS phase on
// distinct (p&1, slot) bank groups (P1 stores degrade to a benign 2-way).
__device__ __forceinline__ int widx(int pos, int quad){
  return (pos << 4) + (((quad ^ (pos >> 1) ^ (pos >> 3)) & 3) << 2);
}

// Butterfly on one pair of positions for 4 rows (2 packed f32x2 lanes each).
// t = {t00,t01,t10,t11} scalar; packed (duplicated) at point of use.
__device__ __forceinline__ void bflyq(u64& x0a, u64& x0b, u64& x1a, u64& x1b,
                                      const float* t){
  u64 m0 = pk2(t[0], t[0]);
  u64 m1 = pk2(t[1], t[1]);
  u64 m2 = pk2(t[2], t[2]);
  u64 m3 = pk2(t[3], t[3]);
  u64 a = x0a, b = x1a;
  x0a = fma2(m0, a, mul2(m1, b));
  x1a = fma2(m2, a, mul2(m3, b));
  a = x0b; b = x1b;
  x0b = fma2(m0, a, mul2(m1, b));
  x1b = fma2(m2, a, mul2(m3, b));
}

// 3 stages on 8 local elements (local strides 1,2,4).
__device__ __forceinline__ void radix8q(u64 v01[8], u64 v23[8], const float tw[48]){
  bflyq(v01[0],v23[0], v01[1],v23[1], tw+ 0);
  bflyq(v01[2],v23[2], v01[3],v23[3], tw+ 4);
  bflyq(v01[4],v23[4], v01[5],v23[5], tw+ 8);
  bflyq(v01[6],v23[6], v01[7],v23[7], tw+12);
  bflyq(v01[0],v23[0], v01[2],v23[2], tw+16);
  bflyq(v01[1],v23[1], v01[3],v23[3], tw+20);
  bflyq(v01[4],v23[4], v01[6],v23[6], tw+24);
  bflyq(v01[5],v23[5], v01[7],v23[7], tw+28);
  bflyq(v01[0],v23[0], v01[4],v23[4], tw+32);
  bflyq(v01[1],v23[1], v01[5],v23[5], tw+36);
  bflyq(v01[2],v23[2], v01[6],v23[6], tw+40);
  bflyq(v01[3],v23[3], v01[7],v23[7], tw+44);
}

__device__ __forceinline__ void load_tw(const float4* __restrict__ tw4,
                                        int s0, int pbase, int pstride, float tw[48]){
  #pragma unroll
  for (int s = 0; s < 3; s++){
    #pragma unroll
    for (int i = 0; i < 4; i++){
      float4 t = tw4[(s0 + s) * 512 + pbase + i * pstride];
      tw[(s*4+i)*4+0] = t.x; tw[(s*4+i)*4+1] = t.y;
      tw[(s*4+i)*4+2] = t.z; tw[(s*4+i)*4+3] = t.w;
    }
  }
}

__global__ __launch_bounds__(256, 2)
void butterfly_kernel(const float* __restrict__ x,
                      const float* __restrict__ twg,
                      const float* __restrict__ bias,
                      float* __restrict__ out)
{
  extern __shared__ float sdata[];   // 1024 pos * 16 rows * 4B = 64KB
  const float4* tw4 = (const float4*)twg;
  const int tid = threadIdx.x;
  const int o   = tid & 127;         // position-octet / position index
  const int sub = tid >> 7;          // which 8 of the 16 rows
  const long long rowbase = (long long)blockIdx.x * 16 + sub * 8;

  float tw[48];

  // ================= PASS 1: stages 0-2 (stride 1,2,4), global -> smem ======
  load_tw(tw4, 0, 4 * o, 1, tw);
  #pragma unroll
  for (int g = 0; g < 2; g++){
    const int quad = 2 * sub + g;
    const float* base = x + (rowbase + 4 * g) * 1024 + 8 * o;
    float4 a0 = *(const float4*)(base        );
    float4 b0 = *(const float4*)(base +    4 );
    float4 a1 = *(const float4*)(base + 1024 );
    float4 b1 = *(const float4*)(base + 1028 );
    float4 a2 = *(const float4*)(base + 2048 );
    float4 b2 = *(const float4*)(base + 2052 );
    float4 a3 = *(const float4*)(base + 3072 );
    float4 b3 = *(const float4*)(base + 3076 );
    u64 v01[8], v23[8];
    v01[0]=pk2(a0.x,a1.x); v01[1]=pk2(a0.y,a1.y); v01[2]=pk2(a0.z,a1.z); v01[3]=pk2(a0.w,a1.w);
    v01[4]=pk2(b0.x,b1.x); v01[5]=pk2(b0.y,b1.y); v01[6]=pk2(b0.z,b1.z); v01[7]=pk2(b0.w,b1.w);
    v23[0]=pk2(a2.x,a3.x); v23[1]=pk2(a2.y,a3.y); v23[2]=pk2(a2.z,a3.z); v23[3]=pk2(a2.w,a3.w);
    v23[4]=pk2(b2.x,b3.x); v23[5]=pk2(b2.y,b3.y); v23[6]=pk2(b2.z,b3.z); v23[7]=pk2(b2.w,b3.w);

    radix8q(v01, v23, tw);

    #pragma unroll
    for (int c = 0; c < 8; c++){
      ulonglong2 u; u.x = v01[c]; u.y = v23[c];
      *(ulonglong2*)&sdata[widx(8 * o + c, quad)] = u;
    }
  }
  __syncthreads();

  // ================= PASS 2: stages 3-5 (stride 8,16,32) ====================
  {
    const int bb = o >> 3, j = o & 7;
    load_tw(tw4, 3, 32 * bb + j, 8, tw);
    #pragma unroll
    for (int g = 0; g < 2; g++){
      const int quad = 2 * sub + g;
      u64 v01[8], v23[8];
      #pragma unroll
      for (int k = 0; k < 8; k++){
        ulonglong2 u = *(ulonglong2*)&sdata[widx(64 * bb + 8 * k + j, quad)];
        v01[k] = u.x; v23[k] = u.y;
      }
      radix8q(v01, v23, tw);
      #pragma unroll
      for (int k = 0; k < 8; k++){
        ulonglong2 u; u.x = v01[k]; u.y = v23[k];
        *(ulonglong2*)&sdata[widx(64 * bb + 8 * k + j, quad)] = u;
      }
    }
  }
  __syncthreads();

  // ================= PASS 3: stages 6-8 (stride 64,128,256) =================
  {
    const int BB = o >> 6, j = o & 63;
    load_tw(tw4, 6, 256 * BB + j, 64, tw);
    #pragma unroll
    for (int g = 0; g < 2; g++){
      const int quad = 2 * sub + g;
      u64 v01[8], v23[8];
      #pragma unroll
      for (int k = 0; k < 8; k++){
        ulonglong2 u = *(ulonglong2*)&sdata[widx(512 * BB + 64 * k + j, quad)];
        v01[k] = u.x; v23[k] = u.y;
      }
      radix8q(v01, v23, tw);
      #pragma unroll
      for (int k = 0; k < 8; k++){
        ulonglong2 u; u.x = v01[k]; u.y = v23[k];
        *(ulonglong2*)&sdata[widx(512 * BB + 64 * k + j, quad)] = u;
      }
    }
  }
  __syncthreads();

  // ================= PASS 4: stage 9 (stride 512) + bias -> global ==========
  {
    float t9[16], bsl[4], bsh[4];
    #pragma unroll
    for (int jj = 0; jj < 4; jj++){
      float4 t = tw4[9 * 512 + o + 128 * jj];
      t9[jj*4+0] = t.x; t9[jj*4+1] = t.y; t9[jj*4+2] = t.z; t9[jj*4+3] = t.w;
      bsl[jj] = bias[o + 128 * jj];
      bsh[jj] = bias[o + 128 * jj + 512];
    }
    #pragma unroll
    for (int g = 0; g < 2; g++){
      const int quad = 2 * sub + g;
      float* orow = out + (rowbase + 4 * g) * 1024;
      #pragma unroll
      for (int jj = 0; jj < 4; jj++){
        const int plo = o + 128 * jj, phi = plo + 512;
        ulonglong2 ulo = *(ulonglong2*)&sdata[widx(plo, quad)];
        ulonglong2 uhi = *(ulonglong2*)&sdata[widx(phi, quad)];
        u64 m0 = pk2(t9[jj*4+0], t9[jj*4+0]);
        u64 m1 = pk2(t9[jj*4+1], t9[jj*4+1]);
        u64 m2 = pk2(t9[jj*4+2], t9[jj*4+2]);
        u64 m3 = pk2(t9[jj*4+3], t9[jj*4+3]);
        u64 bl = pk2(bsl[jj], bsl[jj]);
        u64 bh = pk2(bsh[jj], bsh[jj]);
        u64 y0a = fma2(m0, ulo.x, fma2(m1, uhi.x, bl));
        u64 y0b = fma2(m0, ulo.y, fma2(m1, uhi.y, bl));
        u64 y1a = fma2(m2, ulo.x, fma2(m3, uhi.x, bh));
        u64 y1b = fma2(m2, ulo.y, fma2(m3, uhi.y, bh));
        float f0, f1, f2, f3;
        upk2(y0a, f0, f1); upk2(y0b, f2, f3);
        orow[0*1024 + plo] = f0; orow[1*1024 + plo] = f1;
        orow[2*1024 + plo] = f2; orow[3*1024 + plo] = f3;
        upk2(y1a, f0, f1); upk2(y1b, f2, f3);
        orow[0*1024 + phi] = f0; orow[1*1024 + phi] = f1;
        orow[2*1024 + phi] = f2; orow[3*1024 + phi] = f3;
      }
    }
  }
}

extern "C" void kernel_launch(void* const* d_in, const int* in_sizes, int n_in,
                              void* d_out, int out_size)
{
  const float* x    = (const float*)d_in[0];   // (32768, 1024) f32
  const float* tw   = (const float*)d_in[1];   // (1, 10, 512, 2, 2) f32
  const float* bias = (const float*)d_in[2];   // (1024,) f32
  float* out = (float*)d_out;                  // (32768, 1024) f32

  const int batch = in_sizes[0] / 1024;
  const int smem_bytes = 1024 * 16 * 4;        // 64KB

  cudaFuncSetAttribute(butterfly_kernel,
                       cudaFuncAttributeMaxDynamicSharedMemorySize, smem_bytes);
  butterfly_kernel<<<batch / 16, 256, smem_bytes>>>(x, tw, bias, out);
}

// round 5
// speedup vs baseline: 1.1373x; 1.0486x over previous
#include <cuda_runtime.h>

typedef unsigned long long u64;

__device__ __forceinline__ u64 pk2(float lo, float hi){
  u64 r; asm volatile("mov.b64 %0, {%1,%2};" : "=l"(r) : "f"(lo), "f"(hi)); return r;
}
__device__ __forceinline__ void upk2(u64 v, float& lo, float& hi){
  asm("mov.b64 {%0,%1}, %2;" : "=f"(lo), "=f"(hi) : "l"(v));
}
__device__ __forceinline__ u64 fma2(u64 a, u64 b, u64 c){
  u64 d; asm("fma.rn.f32x2 %0, %1, %2, %3;" : "=l"(d) : "l"(a), "l"(b), "l"(c)); return d;
}
__device__ __forceinline__ u64 mul2(u64 a, u64 b){
  u64 d; asm("mul.rn.f32x2 %0, %1, %2;" : "=l"(d) : "l"(a), "l"(b)); return d;
}
__device__ __forceinline__ u64 add2(u64 a, u64 b){
  u64 d; asm("add.rn.f32x2 %0, %1, %2;" : "=l"(d) : "l"(a), "l"(b)); return d;
}

// 16 rows per CTA stored as 4 quads of 4 rows; one 16B slot per (position, quad).
// slot = (quad ^ (p>>1) ^ (p>>3)) & 3 keeps every pass's 8-lane LDS phase on
// distinct (p&1, slot) bank groups (P1 stores degrade to a benign 2-way).
__device__ __forceinline__ int widx(int pos, int quad){
  return (pos << 4) + (((quad ^ (pos >> 1) ^ (pos >> 3)) & 3) << 2);
}

// Butterfly on one pair of positions for 4 rows (2 packed f32x2 lanes each).
// t = {t00,t01,t10,t11} scalar; packed (duplicated) at point of use.
__device__ __forceinline__ void bflyq(u64& x0a, u64& x0b, u64& x1a, u64& x1b,
                                      const float* t){
  u64 m0 = pk2(t[0], t[0]);
  u64 m1 = pk2(t[1], t[1]);
  u64 m2 = pk2(t[2], t[2]);
  u64 m3 = pk2(t[3], t[3]);
  u64 a = x0a, b = x1a;
  x0a = fma2(m0, a, mul2(m1, b));
  x1a = fma2(m2, a, mul2(m3, b));
  a = x0b; b = x1b;
  x0b = fma2(m0, a, mul2(m1, b));
  x1b = fma2(m2, a, mul2(m3, b));
}

// 3 stages on 8 local elements (local strides 1,2,4).
__device__ __forceinline__ void radix8q(u64 v01[8], u64 v23[8], const float tw[48]){
  bflyq(v01[0],v23[0], v01[1],v23[1], tw+ 0);
  bflyq(v01[2],v23[2], v01[3],v23[3], tw+ 4);
  bflyq(v01[4],v23[4], v01[5],v23[5], tw+ 8);
  bflyq(v01[6],v23[6], v01[7],v23[7], tw+12);
  bflyq(v01[0],v23[0], v01[2],v23[2], tw+16);
  bflyq(v01[1],v23[1], v01[3],v23[3], tw+20);
  bflyq(v01[4],v23[4], v01[6],v23[6], tw+24);
  bflyq(v01[5],v23[5], v01[7],v23[7], tw+28);
  bflyq(v01[0],v23[0], v01[4],v23[4], tw+32);
  bflyq(v01[1],v23[1], v01[5],v23[5], tw+36);
  bflyq(v01[2],v23[2], v01[6],v23[6], tw+40);
  bflyq(v01[3],v23[3], v01[7],v23[7], tw+44);
}

__device__ __forceinline__ void load_tw(const float4* __restrict__ tw4,
                                        int s0, int pbase, int pstride, float tw[48]){
  #pragma unroll
  for (int s = 0; s < 3; s++){
    #pragma unroll
    for (int i = 0; i < 4; i++){
      float4 t = tw4[(s0 + s) * 512 + pbase + i * pstride];
      tw[(s*4+i)*4+0] = t.x; tw[(s*4+i)*4+1] = t.y;
      tw[(s*4+i)*4+2] = t.z; tw[(s*4+i)*4+3] = t.w;
    }
  }
}

__global__ __launch_bounds__(256, 2)
void butterfly_kernel(const float* __restrict__ x,
                      const float* __restrict__ twg,
                      const float* __restrict__ bias,
                      float* __restrict__ out)
{
  extern __shared__ float sdata[];   // 1024 pos * 16 rows * 4B = 64KB
  const float4* tw4 = (const float4*)twg;
  const int tid = threadIdx.x;
  const int o   = tid & 127;         // position-octet index (P1/P2)
  const int sub = tid >> 7;          // which 8 of the 16 rows (P1/P2)
  const long long rowbase = (long long)blockIdx.x * 16 + sub * 8;

  float tw[48];

  // ================= PASS 1: stages 0-2 (stride 1,2,4), global -> smem ======
  load_tw(tw4, 0, 4 * o, 1, tw);
  #pragma unroll
  for (int g = 0; g < 2; g++){
    const int quad = 2 * sub + g;    // quad q holds rows blk*16 + 4q + {0..3}
    const float* base = x + (rowbase + 4 * g) * 1024 + 8 * o;
    float4 a0 = *(const float4*)(base        );
    float4 b0 = *(const float4*)(base +    4 );
    float4 a1 = *(const float4*)(base + 1024 );
    float4 b1 = *(const float4*)(base + 1028 );
    float4 a2 = *(const float4*)(base + 2048 );
    float4 b2 = *(const float4*)(base + 2052 );
    float4 a3 = *(const float4*)(base + 3072 );
    float4 b3 = *(const float4*)(base + 3076 );
    u64 v01[8], v23[8];
    v01[0]=pk2(a0.x,a1.x); v01[1]=pk2(a0.y,a1.y); v01[2]=pk2(a0.z,a1.z); v01[3]=pk2(a0.w,a1.w);
    v01[4]=pk2(b0.x,b1.x); v01[5]=pk2(b0.y,b1.y); v01[6]=pk2(b0.z,b1.z); v01[7]=pk2(b0.w,b1.w);
    v23[0]=pk2(a2.x,a3.x); v23[1]=pk2(a2.y,a3.y); v23[2]=pk2(a2.z,a3.z); v23[3]=pk2(a2.w,a3.w);
    v23[4]=pk2(b2.x,b3.x); v23[5]=pk2(b2.y,b3.y); v23[6]=pk2(b2.z,b3.z); v23[7]=pk2(b2.w,b3.w);

    radix8q(v01, v23, tw);

    #pragma unroll
    for (int c = 0; c < 8; c++){
      ulonglong2 u; u.x = v01[c]; u.y = v23[c];
      *(ulonglong2*)&sdata[widx(8 * o + c, quad)] = u;
    }
  }
  __syncthreads();

  // ================= PASS 2: stages 3-5 (stride 8,16,32) ====================
  {
    const int bb = o >> 3, j = o & 7;
    load_tw(tw4, 3, 32 * bb + j, 8, tw);
    #pragma unroll
    for (int g = 0; g < 2; g++){
      const int quad = 2 * sub + g;
      u64 v01[8], v23[8];
      #pragma unroll
      for (int k = 0; k < 8; k++){
        ulonglong2 u = *(ulonglong2*)&sdata[widx(64 * bb + 8 * k + j, quad)];
        v01[k] = u.x; v23[k] = u.y;
      }
      radix8q(v01, v23, tw);
      #pragma unroll
      for (int k = 0; k < 8; k++){
        ulonglong2 u; u.x = v01[k]; u.y = v23[k];
        *(ulonglong2*)&sdata[widx(64 * bb + 8 * k + j, quad)] = u;
      }
    }
  }
  __syncthreads();

  // ====== PASS 3: stages 6-9 (stride 64,128,256,512) + bias -> global =======
  // Thread owns pos = j + 64m, m=0..15, for one quad (4 rows). All four
  // stages run in registers; smem is read exactly once.
  {
    const int j = tid & 63;
    const int q = tid >> 6;
    u64 v01[16], v23[16];
    #pragma unroll
    for (int m = 0; m < 16; m++){
      ulonglong2 u = *(ulonglong2*)&sdata[widx(j + 64 * m, q)];
      v01[m] = u.x; v23[m] = u.y;
    }
    // stage 6 (S=64): pairs (2r, 2r+1); tw idx = 64r + j
    #pragma unroll
    for (int r = 0; r < 8; r++){
      float4 t = tw4[6 * 512 + 64 * r + j];
      float tm[4] = {t.x, t.y, t.z, t.w};
      bflyq(v01[2*r], v23[2*r], v01[2*r+1], v23[2*r+1], tm);
    }
    // stage 7 (S=128): pairs (4r+h, 4r+h+2); tw idx = 128r + 64h + j
    #pragma unroll
    for (int r = 0; r < 4; r++){
      #pragma unroll
      for (int h = 0; h < 2; h++){
        float4 t = tw4[7 * 512 + 128 * r + 64 * h + j];
        float tm[4] = {t.x, t.y, t.z, t.w};
        const int m0 = 4 * r + h;
        bflyq(v01[m0], v23[m0], v01[m0+2], v23[m0+2], tm);
      }
    }
    // stage 8 (S=256): pairs (8r+h, 8r+h+4); tw idx = 256r + 64h + j
    #pragma unroll
    for (int r = 0; r < 2; r++){
      #pragma unroll
      for (int h = 0; h < 4; h++){
        float4 t = tw4[8 * 512 + 256 * r + 64 * h + j];
        float tm[4] = {t.x, t.y, t.z, t.w};
        const int m0 = 8 * r + h;
        bflyq(v01[m0], v23[m0], v01[m0+4], v23[m0+4], tm);
      }
    }
    // stage 9 (S=512): pairs (h, h+8); tw idx = 64h + j
    #pragma unroll
    for (int h = 0; h < 8; h++){
      float4 t = tw4[9 * 512 + 64 * h + j];
      float tm[4] = {t.x, t.y, t.z, t.w};
      bflyq(v01[h], v23[h], v01[h+8], v23[h+8], tm);
    }
    // bias + store (lanes j consecutive -> 128B-coalesced STG.32)
    const long long r0 = (long long)blockIdx.x * 16 + 4 * q;
    float* obase = out + r0 * 1024 + j;
    #pragma unroll
    for (int m = 0; m < 16; m++){
      float b = bias[j + 64 * m];
      u64 b2 = pk2(b, b);
      u64 ylo = add2(v01[m], b2);
      u64 yhi = add2(v23[m], b2);
      float f0, f1, f2, f3;
      upk2(ylo, f0, f1); upk2(yhi, f2, f3);
      float* op = obase + 64 * m;
      op[0]    = f0;
      op[1024] = f1;
      op[2048] = f2;
      op[3072] = f3;
    }
  }
}

extern "C" void kernel_launch(void* const* d_in, const int* in_sizes, int n_in,
                              void* d_out, int out_size)
{
  const float* x    = (const float*)d_in[0];   // (32768, 1024) f32
  const float* tw   = (const float*)d_in[1];   // (1, 10, 512, 2, 2) f32
  const float* bias = (const float*)d_in[2];   // (1024,) f32
  float* out = (float*)d_out;                  // (32768, 1024) f32

  const int batch = in_sizes[0] / 1024;
  const int smem_bytes = 1024 * 16 * 4;        // 64KB

  cudaFuncSetAttribute(butterfly_kernel,
                       cudaFuncAttributeMaxDynamicSharedMemorySize, smem_bytes);
  butterfly_kernel<<<batch / 16, 256, smem_bytes>>>(x, tw, bias, out);
}